// round 3
// baseline (speedup 1.0000x reference)
#include <cuda_runtime.h>
#include <cstdint>

// Problem constants
#define NB      2
#define CIN     64
#define COUT    64
#define HH      768
#define WW      768
#define BSIZE   50
#define BOUT    48
#define BSTR    48
#define BN_EPS  1e-3f

#define CK      8      // cin chunk
#define THREADS 512

// Device scratch (no allocations allowed)
__device__ float g_wT[576 * 64];   // [q = ci*9 + k][co]
__device__ float g_scale[64];
__device__ float g_bias[64];
__device__ int   g_mask[512];

// ---------------------------------------------------------------------------
// prep: transpose weights to [K][cout] layout, fold BN into scale/bias
// ---------------------------------------------------------------------------
__global__ void prep_kernel(const float* __restrict__ w,
                            const float* __restrict__ conv_b,
                            const float* __restrict__ gamma,
                            const float* __restrict__ beta,
                            const float* __restrict__ mean,
                            const float* __restrict__ var) {
    int tid = blockIdx.x * blockDim.x + threadIdx.x;
    for (int i = tid; i < 576 * 64; i += gridDim.x * blockDim.x) {
        int co = i & 63;
        int q  = i >> 6;
        g_wT[i] = w[co * 576 + q];
    }
    if (tid < 64) {
        float inv = gamma[tid] * rsqrtf(var[tid] + BN_EPS);
        g_scale[tid] = inv;
        g_bias[tid]  = beta[tid] + (conv_b[tid] - mean[tid]) * inv;
    }
}

// ---------------------------------------------------------------------------
// mask: mark active logical blocks (n*256 + bh*16 + bw)
// ---------------------------------------------------------------------------
__global__ void mask_kernel(const int* __restrict__ abi, int nblk) {
    int t = threadIdx.x;
    if (t < 512) g_mask[t] = 0;
    __syncthreads();
    if (t < nblk) {
        int n  = abi[3 * t + 0];
        int bh = abi[3 * t + 1];
        int bw = abi[3 * t + 2];
        g_mask[(n << 8) + (bh << 4) + bw] = 1;
    }
}

// ---------------------------------------------------------------------------
// zero: write zeros to the INACTIVE block regions only (disjoint from conv)
// grid (512, 4), 256 threads; blockIdx.y selects 16 channels
// ---------------------------------------------------------------------------
__global__ void zero_kernel(float* __restrict__ out) {
    int blk = blockIdx.x;
    if (g_mask[blk]) return;
    int n  = blk >> 8;
    int bh = (blk >> 4) & 15;
    int bw = blk & 15;
    int cbase = blockIdx.y * 16;
    const float4 z = make_float4(0.f, 0.f, 0.f, 0.f);
    // 16 ch * 48 rows * 12 float4 per row
    for (int i = threadIdx.x; i < 16 * 48 * 12; i += blockDim.x) {
        int q   = i % 12;
        int row = (i / 12) % 48;
        int c   = cbase + i / (12 * 48);
        float4* p = reinterpret_cast<float4*>(
            out + (((size_t)(n * COUT + c) * HH + bh * 48 + row) * WW + bw * 48)) + q;
        *p = z;
    }
}

// ---------------------------------------------------------------------------
// conv: one CTA = one active block x 8 output rows x 48 cols x 64 cout.
// 512 threads; thread = 6 positions x 8 cout, packed into 24 f32x2 accumulators.
// ---------------------------------------------------------------------------
__global__ __launch_bounds__(THREADS, 1)
void conv_kernel(const float* __restrict__ x,
                 const int*   __restrict__ abi,
                 float*       __restrict__ out) {
    __shared__ __align__(16) float s_in[CK][10][52];  // [ci][row][col] (50 used)
    __shared__ __align__(16) float s_w[CK][9][64];    // [ci][kh*3+kw][co]
    __shared__ float s_scale[64];
    __shared__ float s_bias[64];

    const int b    = blockIdx.y;
    const int tile = blockIdx.x;        // 0..5 : 8-row strip
    const int tid  = threadIdx.x;

    const int n  = abi[3 * b + 0];
    const int bh = abi[3 * b + 1];
    const int bw = abi[3 * b + 2];

    if (tid < 64) { s_scale[tid] = g_scale[tid]; s_bias[tid] = g_bias[tid]; }

    const int co_g = tid & 7;            // 8 cout groups of 8
    const int w_g  = (tid >> 3) & 7;     // 8 width groups of 6
    const int row  = tid >> 6;           // 0..7 output rows in strip
    const int co8  = co_g * 8;
    const int wg6  = w_g * 6;

    const int base_r = bh * BSTR + tile * 8 - 1;  // unpadded top input row
    const int base_c = bw * BSTR - 1;             // unpadded left input col

    unsigned long long acc[6][4];
    #pragma unroll
    for (int p = 0; p < 6; p++)
        #pragma unroll
        for (int q = 0; q < 4; q++) acc[p][q] = 0ULL;

    for (int cc = 0; cc < CIN / CK; cc++) {
        __syncthreads();
        // ---- load input tile: 8 cin x 10 rows x 50 cols ----
        for (int i = tid; i < CK * 10 * 50; i += THREADS) {
            int c  = i % 50;
            int r  = (i / 50) % 10;
            int ci = i / 500;
            int gr = base_r + r;
            int gc = base_c + c;
            float v = 0.f;
            if ((unsigned)gr < (unsigned)HH && (unsigned)gc < (unsigned)WW)
                v = x[((size_t)(n * CIN + cc * CK + ci) * HH + gr) * WW + gc];
            s_in[ci][r][c] = v;
        }
        // ---- load weight chunk: contiguous 72*64 floats, conflict-free ----
        const float* wsrc = g_wT + cc * (CK * 9 * 64);
        float* wdst = &s_w[0][0][0];
        for (int i = tid; i < CK * 9 * 64; i += THREADS)
            wdst[i] = wsrc[i];
        __syncthreads();

        // ---- compute ----
        #pragma unroll
        for (int ci = 0; ci < CK; ci++) {
            #pragma unroll
            for (int kh = 0; kh < 3; kh++) {
                unsigned long long xd[8];
                #pragma unroll
                for (int j = 0; j < 8; j++) {
                    float xv = s_in[ci][row + kh][wg6 + j];
                    asm("mov.b64 %0, {%1, %1};" : "=l"(xd[j]) : "f"(xv));
                }
                #pragma unroll
                for (int kw = 0; kw < 3; kw++) {
                    const float4* wp =
                        reinterpret_cast<const float4*>(&s_w[ci][kh * 3 + kw][co8]);
                    float4 w0 = wp[0];
                    float4 w1 = wp[1];
                    unsigned long long wq[4];
                    asm("mov.b64 %0, {%1, %2};" : "=l"(wq[0]) : "f"(w0.x), "f"(w0.y));
                    asm("mov.b64 %0, {%1, %2};" : "=l"(wq[1]) : "f"(w0.z), "f"(w0.w));
                    asm("mov.b64 %0, {%1, %2};" : "=l"(wq[2]) : "f"(w1.x), "f"(w1.y));
                    asm("mov.b64 %0, {%1, %2};" : "=l"(wq[3]) : "f"(w1.z), "f"(w1.w));
                    #pragma unroll
                    for (int p = 0; p < 6; p++) {
                        #pragma unroll
                        for (int q = 0; q < 4; q++) {
                            asm("fma.rn.f32x2 %0, %1, %2, %0;"
                                : "+l"(acc[p][q])
                                : "l"(xd[p + kw]), "l"(wq[q]));
                        }
                    }
                }
            }
        }
    }

    // ---- epilogue: BN fold + ReLU + store ----
    const int orow  = bh * BSTR + tile * 8 + row;
    const int ocolb = bw * BSTR + wg6;
    #pragma unroll
    for (int q = 0; q < 4; q++) {
        int c0 = co8 + 2 * q;
        int c1 = c0 + 1;
        float s0 = s_scale[c0], b0 = s_bias[c0];
        float s1 = s_scale[c1], b1 = s_bias[c1];
        #pragma unroll
        for (int p = 0; p < 6; p++) {
            float lo, hi;
            asm("mov.b64 {%0, %1}, %2;" : "=f"(lo), "=f"(hi) : "l"(acc[p][q]));
            float v0 = fmaxf(fmaf(lo, s0, b0), 0.f);
            float v1 = fmaxf(fmaf(hi, s1, b1), 0.f);
            out[((size_t)(n * COUT + c0) * HH + orow) * WW + ocolb + p] = v0;
            out[((size_t)(n * COUT + c1) * HH + orow) * WW + ocolb + p] = v1;
        }
    }
}

// ---------------------------------------------------------------------------
extern "C" void kernel_launch(void* const* d_in, const int* in_sizes, int n_in,
                              void* d_out, int out_size) {
    const float* x      = (const float*)d_in[0];
    const float* conv_w = (const float*)d_in[1];
    const float* conv_b = (const float*)d_in[2];
    const float* gamma  = (const float*)d_in[3];
    const float* beta   = (const float*)d_in[4];
    const float* rmean  = (const float*)d_in[5];
    const float* rvar   = (const float*)d_in[6];
    const int*   abi    = (const int*)d_in[7];
    float* out = (float*)d_out;

    int nblk = in_sizes[7] / 3;   // 256

    prep_kernel<<<36, 1024>>>(conv_w, conv_b, gamma, beta, rmean, rvar);
    mask_kernel<<<1, 512>>>(abi, nblk);
    zero_kernel<<<dim3(512, 4), 256>>>(out);
    conv_kernel<<<dim3(6, nblk), THREADS>>>(x, abi, out);
}

// round 8
// speedup vs baseline: 3.1731x; 3.1731x over previous
#include <cuda_runtime.h>
#include <cuda_fp16.h>
#include <cstdint>

#define HH      768
#define WW      768
#define BN_EPS  1e-3f

// ---------------- device scratch (no allocations allowed) -------------------
__device__ __half g_patch[256ULL * 50 * 50 * 64];  // [blk][r][c][ci] fp16 NHWC patches
__device__ __half g_wh[9 * 64 * 64];               // [j][co][ci], XOR-swizzled rows
__device__ float  g_scale[64];
__device__ float  g_bias[64];
__device__ int    g_mask[512];

__device__ __forceinline__ uint32_t s2u(const void* p) {
    uint32_t a;
    asm("{ .reg .u64 t; cvta.to.shared.u64 t, %1; cvt.u32.u64 %0, t; }"
        : "=r"(a) : "l"(p));
    return a;
}

// smem map (bytes, dynamic)
#define OFF_SCALE  0
#define OFF_BIAS   256
#define OFF_B      1024        // 9 * 8192 = 73728
#define OFF_A0     74752       // 16384
#define OFF_A1     91136       // 16384
#define SMEM_TOTAL 107520

// ---------------------------------------------------------------------------
// prep: swizzled fp16 weights [j][co][ci], BN folded scale/bias
// ---------------------------------------------------------------------------
__global__ void prep_kernel(const float* __restrict__ w,
                            const float* __restrict__ conv_b,
                            const float* __restrict__ gamma,
                            const float* __restrict__ beta,
                            const float* __restrict__ mean,
                            const float* __restrict__ var) {
    int tid = blockIdx.x * blockDim.x + threadIdx.x;
    for (int i = tid; i < 9 * 64 * 64; i += gridDim.x * blockDim.x) {
        int ci = i & 63, co = (i >> 6) & 63, j = i >> 12;
        int kh = j / 3, kw = j % 3;
        float v = w[((co * 64 + ci) * 3 + kh) * 3 + kw];
        int u  = ci >> 3;
        int su = u ^ (co & 7);               // XOR swizzle within 128B row
        g_wh[j * 4096 + co * 64 + su * 8 + (ci & 7)] = __float2half_rn(v);
    }
    if (tid < 64) {
        float inv = gamma[tid] * rsqrtf(var[tid] + BN_EPS);
        g_scale[tid] = inv;
        g_bias[tid]  = beta[tid] + (conv_b[tid] - mean[tid]) * inv;
    }
}

// ---------------------------------------------------------------------------
__global__ void mask_kernel(const int* __restrict__ abi, int nblk) {
    int t = threadIdx.x;
    if (t < 512) g_mask[t] = 0;
    __syncthreads();
    if (t < nblk) {
        int n = abi[3 * t], bh = abi[3 * t + 1], bw = abi[3 * t + 2];
        g_mask[(n << 8) + (bh << 4) + bw] = 1;
    }
}

// ---------------------------------------------------------------------------
__global__ void zero_kernel(float* __restrict__ out) {
    int blk = blockIdx.x;
    if (g_mask[blk]) return;
    int n = blk >> 8, bh = (blk >> 4) & 15, bw = blk & 15;
    int cbase = blockIdx.y * 16;
    const float4 z = make_float4(0.f, 0.f, 0.f, 0.f);
    for (int i = threadIdx.x; i < 16 * 48 * 12; i += blockDim.x) {
        int q = i % 12, row = (i / 12) % 48, c = cbase + i / (12 * 48);
        float4* p = reinterpret_cast<float4*>(
            out + (((size_t)(n * 64 + c) * HH + bh * 48 + row) * WW + bw * 48)) + q;
        *p = z;
    }
}

// ---------------------------------------------------------------------------
// patch: gather active-block input (with pad-halo) into NHWC fp16 patches
// ---------------------------------------------------------------------------
__global__ __launch_bounds__(256)
void patch_kernel(const float* __restrict__ x, const int* __restrict__ abi) {
    __shared__ __half s[50][64];
    const int r = blockIdx.x, b = blockIdx.y;
    const int n = abi[3 * b], bh = abi[3 * b + 1], bw = abi[3 * b + 2];
    const int gr  = bh * 48 - 1 + r;
    const int gc0 = bw * 48 - 1;
    const bool rok = (unsigned)gr < (unsigned)HH;
    for (int i = threadIdx.x; i < 64 * 50; i += blockDim.x) {
        int ci = i / 50, c = i % 50;
        int gc = gc0 + c;
        float v = 0.f;
        if (rok && (unsigned)gc < (unsigned)WW)
            v = x[((size_t)(n * 64 + ci) * HH + gr) * WW + gc];
        s[c][ci] = __float2half_rn(v);
    }
    __syncthreads();
    __half2* dst = reinterpret_cast<__half2*>(g_patch + ((size_t)(b * 50 + r) * 50) * 64);
    const __half2* ss = reinterpret_cast<const __half2*>(&s[0][0]);
    for (int i = threadIdx.x; i < 50 * 32; i += blockDim.x)
        dst[i] = ss[i];
}

// ---------------------------------------------------------------------------
// conv: implicit GEMM via mma.sync m16n8k16 fp16. CTA = half-block
// (9 M-tiles of 128 pos x 64 cout), 8 warps (4 m x 2 n), warp tile 32x32.
// ---------------------------------------------------------------------------
__global__ void __launch_bounds__(256, 2)
conv_kernel(const int* __restrict__ abi, float* __restrict__ out) {
    extern __shared__ __align__(1024) char smem[];
    const uint32_t sb = s2u(smem);
    const int tid = threadIdx.x;
    const int b = blockIdx.y;
    const int n = abi[3 * b], bh = abi[3 * b + 1], bw = abi[3 * b + 2];

    // stage all 9 weight chunks (73728 B), layout already swizzled
    {
        const uint4* src = reinterpret_cast<const uint4*>(g_wh);
        uint4* dst = reinterpret_cast<uint4*>(smem + OFF_B);
        #pragma unroll
        for (int i = 0; i < 18; i++) dst[tid + 256 * i] = src[tid + 256 * i];
    }
    if (tid < 64) {
        reinterpret_cast<float*>(smem + OFF_SCALE)[tid] = g_scale[tid];
        reinterpret_cast<float*>(smem + OFF_BIAS)[tid]  = g_bias[tid];
    }

    const int lane = tid & 31;
    const int w    = tid >> 5;
    const int m_warp = w & 3;        // 4 m-warps of 32 rows
    const int n_warp = w >> 2;       // 2 n-warps of 32 cols

    // A-load map: row = tid>>1, 4 sixteen-byte units starting at (tid&1)*4
    const int arow = tid >> 1;
    const int au0  = (tid & 1) * 4;
    uint32_t adst[4];
    #pragma unroll
    for (int u = 0; u < 4; u++)
        adst[u] = (uint32_t)(arow * 128 + (((au0 + u) ^ (arow & 7)) * 16));

    // ldmatrix source addresses (swizzled), as offsets within an A/B buffer
    const int a_r = lane & 15;           // fragment row
    const int a_uh = lane >> 4;          // k-half selector
    const int b_n  = (lane & 7) + ((lane >> 4) << 3);
    const int b_uh = (lane >> 3) & 1;

    for (int tl = 0; tl < 9; tl++) {
        const int tile = blockIdx.x * 9 + tl;
        const int p    = tile * 128 + arow;
        const int orow = p / 48, ocol = p - orow * 48;
        const __half* prow = g_patch + (((size_t)b * 50 + orow) * 50 + ocol) * 64;
        uint64_t gsrc;
        asm("cvta.to.global.u64 %0, %1;" : "=l"(gsrc) : "l"(prow));
        gsrc += (uint64_t)au0 * 16;

        float d[2][4][4];
        #pragma unroll
        for (int a = 0; a < 2; a++)
            #pragma unroll
            for (int c = 0; c < 4; c++)
                #pragma unroll
                for (int e = 0; e < 4; e++) d[a][c][e] = 0.f;

        // prologue: load j=0 into buf0
        {
            const uint32_t ab = sb + OFF_A0;
            #pragma unroll
            for (int u = 0; u < 4; u++)
                asm volatile("cp.async.cg.shared.global [%0], [%1], 16;"
                             :: "r"(ab + adst[u]), "l"(gsrc + (uint64_t)u * 16) : "memory");
            asm volatile("cp.async.commit_group;" ::: "memory");
        }

        #pragma unroll
        for (int j = 0; j < 9; j++) {
            if (j < 8) {
                const int jn = j + 1;
                const int kh = jn / 3, kw = jn - kh * 3;
                const uint32_t ab = sb + ((jn & 1) ? OFF_A1 : OFF_A0);
                const uint64_t src = gsrc + (uint64_t)(kh * 50 + kw) * 128;
                #pragma unroll
                for (int u = 0; u < 4; u++)
                    asm volatile("cp.async.cg.shared.global [%0], [%1], 16;"
                                 :: "r"(ab + adst[u]), "l"(src + (uint64_t)u * 16) : "memory");
                asm volatile("cp.async.commit_group;" ::: "memory");
                asm volatile("cp.async.wait_group 1;" ::: "memory");
            } else {
                asm volatile("cp.async.wait_group 0;" ::: "memory");
            }
            __syncthreads();

            const uint32_t abase = sb + ((j & 1) ? OFF_A1 : OFF_A0);
            const uint32_t bbase = sb + OFF_B + j * 8192;

            #pragma unroll
            for (int ks = 0; ks < 4; ks++) {
                // ---- A fragments: 2 m16 tiles ----
                uint32_t a0[4], a1[4];
                {
                    int r0 = m_warp * 32 + a_r;
                    uint32_t addr = abase + (uint32_t)(r0 * 128 +
                                    (((ks * 2 + a_uh) ^ (r0 & 7)) * 16));
                    asm volatile("ldmatrix.sync.aligned.m8n8.x4.shared.b16 "
                                 "{%0,%1,%2,%3}, [%4];"
                                 : "=r"(a0[0]), "=r"(a0[1]), "=r"(a0[2]), "=r"(a0[3])
                                 : "r"(addr));
                    int r1 = r0 + 16;
                    addr = abase + (uint32_t)(r1 * 128 +
                           (((ks * 2 + a_uh) ^ (r1 & 7)) * 16));
                    asm volatile("ldmatrix.sync.aligned.m8n8.x4.shared.b16 "
                                 "{%0,%1,%2,%3}, [%4];"
                                 : "=r"(a1[0]), "=r"(a1[1]), "=r"(a1[2]), "=r"(a1[3])
                                 : "r"(addr));
                }
                // ---- B fragments: 4 n8 tiles via 2 x4 (non-trans!) loads ----
                // B smem is [n][k] (k contiguous) -> mma's "col" B fragment
                // (pairs consecutive in k for fixed n) is the NON-trans form.
                uint32_t bf[4][2];
                {
                    int nn = n_warp * 32 + b_n;
                    uint32_t addr = bbase + (uint32_t)(nn * 128 +
                                    (((ks * 2 + b_uh) ^ (nn & 7)) * 16));
                    asm volatile("ldmatrix.sync.aligned.m8n8.x4.shared.b16 "
                                 "{%0,%1,%2,%3}, [%4];"
                                 : "=r"(bf[0][0]), "=r"(bf[0][1]),
                                   "=r"(bf[1][0]), "=r"(bf[1][1])
                                 : "r"(addr));
                    nn += 16;
                    addr = bbase + (uint32_t)(nn * 128 +
                           (((ks * 2 + b_uh) ^ (nn & 7)) * 16));
                    asm volatile("ldmatrix.sync.aligned.m8n8.x4.shared.b16 "
                                 "{%0,%1,%2,%3}, [%4];"
                                 : "=r"(bf[2][0]), "=r"(bf[2][1]),
                                   "=r"(bf[3][0]), "=r"(bf[3][1])
                                 : "r"(addr));
                }
                // ---- 8 MMAs ----
                #pragma unroll
                for (int nt = 0; nt < 4; nt++) {
                    asm volatile("mma.sync.aligned.m16n8k16.row.col.f32.f16.f16.f32 "
                                 "{%0,%1,%2,%3}, {%4,%5,%6,%7}, {%8,%9}, {%0,%1,%2,%3};"
                                 : "+f"(d[0][nt][0]), "+f"(d[0][nt][1]),
                                   "+f"(d[0][nt][2]), "+f"(d[0][nt][3])
                                 : "r"(a0[0]), "r"(a0[1]), "r"(a0[2]), "r"(a0[3]),
                                   "r"(bf[nt][0]), "r"(bf[nt][1]));
                    asm volatile("mma.sync.aligned.m16n8k16.row.col.f32.f16.f16.f32 "
                                 "{%0,%1,%2,%3}, {%4,%5,%6,%7}, {%8,%9}, {%0,%1,%2,%3};"
                                 : "+f"(d[1][nt][0]), "+f"(d[1][nt][1]),
                                   "+f"(d[1][nt][2]), "+f"(d[1][nt][3])
                                 : "r"(a1[0]), "r"(a1[1]), "r"(a1[2]), "r"(a1[3]),
                                   "r"(bf[nt][0]), "r"(bf[nt][1]));
                }
            }
            __syncthreads();
        }

        // ---- epilogue: BN + ReLU + store ----
        const float* ssc = reinterpret_cast<const float*>(smem + OFF_SCALE);
        const float* sbi = reinterpret_cast<const float*>(smem + OFF_BIAS);
        #pragma unroll
        for (int m16 = 0; m16 < 2; m16++) {
            #pragma unroll
            for (int nt = 0; nt < 4; nt++) {
                #pragma unroll
                for (int e = 0; e < 4; e++) {
                    int rloc = m_warp * 32 + m16 * 16 + (lane >> 2) + ((e >> 1) << 3);
                    int c    = n_warp * 32 + nt * 8 + (lane & 3) * 2 + (e & 1);
                    int pp   = tile * 128 + rloc;
                    int r0   = pp / 48;
                    int er   = bh * 48 + r0;
                    int ec   = bw * 48 + (pp - r0 * 48);
                    float v  = fmaxf(fmaf(d[m16][nt][e], ssc[c], sbi[c]), 0.f);
                    out[((size_t)(n * 64 + c) * HH + er) * WW + ec] = v;
                }
            }
        }
    }
}

// ---------------------------------------------------------------------------
extern "C" void kernel_launch(void* const* d_in, const int* in_sizes, int n_in,
                              void* d_out, int out_size) {
    const float* x      = (const float*)d_in[0];
    const float* conv_w = (const float*)d_in[1];
    const float* conv_b = (const float*)d_in[2];
    const float* gamma  = (const float*)d_in[3];
    const float* beta   = (const float*)d_in[4];
    const float* rmean  = (const float*)d_in[5];
    const float* rvar   = (const float*)d_in[6];
    const int*   abi    = (const int*)d_in[7];
    float* out = (float*)d_out;

    int nblk = in_sizes[7] / 3;   // 256

    cudaFuncSetAttribute(conv_kernel,
                         cudaFuncAttributeMaxDynamicSharedMemorySize, SMEM_TOTAL);

    prep_kernel<<<36, 1024>>>(conv_w, conv_b, gamma, beta, rmean, rvar);
    mask_kernel<<<1, 512>>>(abi, nblk);
    zero_kernel<<<dim3(512, 4), 256>>>(out);
    patch_kernel<<<dim3(50, nblk), 256>>>(x, abi);
    conv_kernel<<<dim3(2, nblk), 256, SMEM_TOTAL>>>(abi, out);
}

// round 9
// speedup vs baseline: 3.6480x; 1.1497x over previous
#include <cuda_runtime.h>
#include <cuda_fp16.h>
#include <cstdint>

#define HH      768
#define WW      768
#define BN_EPS  1e-3f

// ---------------- device scratch (no allocations allowed) -------------------
__device__ __half g_patch[256ULL * 50 * 50 * 64];  // [blk][r][c][ci] fp16 NHWC patches
__device__ __half g_wh[9 * 64 * 64];               // [j][co][ci], XOR-swizzled rows
__device__ float  g_scale[64];
__device__ float  g_bias[64];
__device__ int    g_mask[512];

__device__ __forceinline__ uint32_t s2u(const void* p) {
    uint32_t a;
    asm("{ .reg .u64 t; cvta.to.shared.u64 t, %1; cvt.u32.u64 %0, t; }"
        : "=r"(a) : "l"(p));
    return a;
}

// smem map (bytes, dynamic)
#define OFF_SCALE  0
#define OFF_BIAS   256
#define OFF_B      1024        // 9 * 8192 = 73728
#define OFF_A0     74752       // 16384
#define OFF_A1     91136       // 16384
#define SMEM_TOTAL 107520

// ---------------------------------------------------------------------------
// prep: swizzled fp16 weights [j][co][ci], BN folded scale/bias
// ---------------------------------------------------------------------------
__global__ void prep_kernel(const float* __restrict__ w,
                            const float* __restrict__ conv_b,
                            const float* __restrict__ gamma,
                            const float* __restrict__ beta,
                            const float* __restrict__ mean,
                            const float* __restrict__ var) {
    int tid = blockIdx.x * blockDim.x + threadIdx.x;
    for (int i = tid; i < 9 * 64 * 64; i += gridDim.x * blockDim.x) {
        int ci = i & 63, co = (i >> 6) & 63, j = i >> 12;
        int kh = j / 3, kw = j % 3;
        float v = w[((co * 64 + ci) * 3 + kh) * 3 + kw];
        int u  = ci >> 3;
        int su = u ^ (co & 7);               // XOR swizzle within 128B row
        g_wh[j * 4096 + co * 64 + su * 8 + (ci & 7)] = __float2half_rn(v);
    }
    if (tid < 64) {
        float inv = gamma[tid] * rsqrtf(var[tid] + BN_EPS);
        g_scale[tid] = inv;
        g_bias[tid]  = beta[tid] + (conv_b[tid] - mean[tid]) * inv;
    }
}

// ---------------------------------------------------------------------------
__global__ void mask_kernel(const int* __restrict__ abi, int nblk) {
    int t = threadIdx.x;
    if (t < 512) g_mask[t] = 0;
    __syncthreads();
    if (t < nblk) {
        int n = abi[3 * t], bh = abi[3 * t + 1], bw = abi[3 * t + 2];
        g_mask[(n << 8) + (bh << 4) + bw] = 1;
    }
}

// ---------------------------------------------------------------------------
__global__ void zero_kernel(float* __restrict__ out) {
    int blk = blockIdx.x;
    if (g_mask[blk]) return;
    int n = blk >> 8, bh = (blk >> 4) & 15, bw = blk & 15;
    int cbase = blockIdx.y * 16;
    const float4 z = make_float4(0.f, 0.f, 0.f, 0.f);
    for (int i = threadIdx.x; i < 16 * 48 * 12; i += blockDim.x) {
        int q = i % 12, row = (i / 12) % 48, c = cbase + i / (12 * 48);
        float4* p = reinterpret_cast<float4*>(
            out + (((size_t)(n * 64 + c) * HH + bh * 48 + row) * WW + bw * 48)) + q;
        *p = z;
    }
}

// ---------------------------------------------------------------------------
// patch: gather active-block input (with pad-halo) into NHWC fp16 patches.
// Conflict-free staging: s[ci][c] (coalesced STS), transpose-out via half2
// (2-way LDS conflict only, coalesced gmem writes).
// ---------------------------------------------------------------------------
__global__ __launch_bounds__(256)
void patch_kernel(const float* __restrict__ x, const int* __restrict__ abi) {
    __shared__ __half s[64][50];
    const int r = blockIdx.x, b = blockIdx.y;
    const int n = abi[3 * b], bh = abi[3 * b + 1], bw = abi[3 * b + 2];
    const int gr  = bh * 48 - 1 + r;
    const int gc0 = bw * 48 - 1;
    const bool rok = (unsigned)gr < (unsigned)HH;

    // phase 1: coalesced gmem read (50-wide rows), coalesced smem write
    for (int i = threadIdx.x; i < 64 * 50; i += 256) {
        int ci = i / 50, c = i - ci * 50;
        int gc = gc0 + c;
        float v = 0.f;
        if (rok && (unsigned)gc < (unsigned)WW)
            v = x[((size_t)(n * 64 + ci) * HH + gr) * WW + gc];
        s[ci][c] = __float2half_rn(v);
    }
    __syncthreads();

    // phase 2: transpose out; consecutive threads -> consecutive half2 stores
    __half2* dst = reinterpret_cast<__half2*>(g_patch + ((size_t)(b * 50 + r) * 50) * 64);
    for (int i = threadIdx.x; i < 50 * 32; i += 256) {
        int c = i >> 5, ci2 = i & 31;
        __half2 h = __halves2half2(s[ci2 * 2][c], s[ci2 * 2 + 1][c]);
        dst[c * 32 + ci2] = h;
    }
}

// ---------------------------------------------------------------------------
// conv: implicit GEMM via mma.sync m16n8k16 fp16. CTA = half-block
// (9 M-tiles of 128 pos x 64 cout), 8 warps (4 m x 2 n), warp tile 32x32.
// ---------------------------------------------------------------------------
__global__ void __launch_bounds__(256, 2)
conv_kernel(const int* __restrict__ abi, float* __restrict__ out) {
    extern __shared__ __align__(1024) char smem[];
    const uint32_t sb = s2u(smem);
    const int tid = threadIdx.x;
    const int b = blockIdx.y;
    const int n = abi[3 * b], bh = abi[3 * b + 1], bw = abi[3 * b + 2];

    // stage all 9 weight chunks (73728 B), layout already swizzled
    {
        const uint4* src = reinterpret_cast<const uint4*>(g_wh);
        uint4* dst = reinterpret_cast<uint4*>(smem + OFF_B);
        #pragma unroll
        for (int i = 0; i < 18; i++) dst[tid + 256 * i] = src[tid + 256 * i];
    }
    if (tid < 64) {
        reinterpret_cast<float*>(smem + OFF_SCALE)[tid] = g_scale[tid];
        reinterpret_cast<float*>(smem + OFF_BIAS)[tid]  = g_bias[tid];
    }

    const int lane = tid & 31;
    const int w    = tid >> 5;
    const int m_warp = w & 3;        // 4 m-warps of 32 rows
    const int n_warp = w >> 2;       // 2 n-warps of 32 cols

    // A-load map: row = tid>>1, 4 sixteen-byte units starting at (tid&1)*4
    const int arow = tid >> 1;
    const int au0  = (tid & 1) * 4;
    uint32_t adst[4];
    #pragma unroll
    for (int u = 0; u < 4; u++)
        adst[u] = (uint32_t)(arow * 128 + (((au0 + u) ^ (arow & 7)) * 16));

    // ldmatrix source addresses (swizzled), as offsets within an A/B buffer
    const int a_r = lane & 15;           // fragment row
    const int a_uh = lane >> 4;          // k-half selector
    const int b_n  = (lane & 7) + ((lane >> 4) << 3);
    const int b_uh = (lane >> 3) & 1;

    for (int tl = 0; tl < 9; tl++) {
        const int tile = blockIdx.x * 9 + tl;
        const int p    = tile * 128 + arow;
        const int orow = p / 48, ocol = p - orow * 48;
        const __half* prow = g_patch + (((size_t)b * 50 + orow) * 50 + ocol) * 64;
        uint64_t gsrc;
        asm("cvta.to.global.u64 %0, %1;" : "=l"(gsrc) : "l"(prow));
        gsrc += (uint64_t)au0 * 16;

        float d[2][4][4];
        #pragma unroll
        for (int a = 0; a < 2; a++)
            #pragma unroll
            for (int c = 0; c < 4; c++)
                #pragma unroll
                for (int e = 0; e < 4; e++) d[a][c][e] = 0.f;

        // prologue: load j=0 into buf0
        {
            const uint32_t ab = sb + OFF_A0;
            #pragma unroll
            for (int u = 0; u < 4; u++)
                asm volatile("cp.async.cg.shared.global [%0], [%1], 16;"
                             :: "r"(ab + adst[u]), "l"(gsrc + (uint64_t)u * 16) : "memory");
            asm volatile("cp.async.commit_group;" ::: "memory");
        }

        #pragma unroll
        for (int j = 0; j < 9; j++) {
            if (j < 8) {
                const int jn = j + 1;
                const int kh = jn / 3, kw = jn - kh * 3;
                const uint32_t ab = sb + ((jn & 1) ? OFF_A1 : OFF_A0);
                const uint64_t src = gsrc + (uint64_t)(kh * 50 + kw) * 128;
                #pragma unroll
                for (int u = 0; u < 4; u++)
                    asm volatile("cp.async.cg.shared.global [%0], [%1], 16;"
                                 :: "r"(ab + adst[u]), "l"(src + (uint64_t)u * 16) : "memory");
                asm volatile("cp.async.commit_group;" ::: "memory");
                asm volatile("cp.async.wait_group 1;" ::: "memory");
            } else {
                asm volatile("cp.async.wait_group 0;" ::: "memory");
            }
            __syncthreads();

            const uint32_t abase = sb + ((j & 1) ? OFF_A1 : OFF_A0);
            const uint32_t bbase = sb + OFF_B + j * 8192;

            #pragma unroll
            for (int ks = 0; ks < 4; ks++) {
                // ---- A fragments: 2 m16 tiles ----
                uint32_t a0[4], a1[4];
                {
                    int r0 = m_warp * 32 + a_r;
                    uint32_t addr = abase + (uint32_t)(r0 * 128 +
                                    (((ks * 2 + a_uh) ^ (r0 & 7)) * 16));
                    asm volatile("ldmatrix.sync.aligned.m8n8.x4.shared.b16 "
                                 "{%0,%1,%2,%3}, [%4];"
                                 : "=r"(a0[0]), "=r"(a0[1]), "=r"(a0[2]), "=r"(a0[3])
                                 : "r"(addr));
                    int r1 = r0 + 16;
                    addr = abase + (uint32_t)(r1 * 128 +
                           (((ks * 2 + a_uh) ^ (r1 & 7)) * 16));
                    asm volatile("ldmatrix.sync.aligned.m8n8.x4.shared.b16 "
                                 "{%0,%1,%2,%3}, [%4];"
                                 : "=r"(a1[0]), "=r"(a1[1]), "=r"(a1[2]), "=r"(a1[3])
                                 : "r"(addr));
                }
                // ---- B fragments: 4 n8 tiles via 2 x4 (non-trans) loads ----
                uint32_t bf[4][2];
                {
                    int nn = n_warp * 32 + b_n;
                    uint32_t addr = bbase + (uint32_t)(nn * 128 +
                                    (((ks * 2 + b_uh) ^ (nn & 7)) * 16));
                    asm volatile("ldmatrix.sync.aligned.m8n8.x4.shared.b16 "
                                 "{%0,%1,%2,%3}, [%4];"
                                 : "=r"(bf[0][0]), "=r"(bf[0][1]),
                                   "=r"(bf[1][0]), "=r"(bf[1][1])
                                 : "r"(addr));
                    nn += 16;
                    addr = bbase + (uint32_t)(nn * 128 +
                           (((ks * 2 + b_uh) ^ (nn & 7)) * 16));
                    asm volatile("ldmatrix.sync.aligned.m8n8.x4.shared.b16 "
                                 "{%0,%1,%2,%3}, [%4];"
                                 : "=r"(bf[2][0]), "=r"(bf[2][1]),
                                   "=r"(bf[3][0]), "=r"(bf[3][1])
                                 : "r"(addr));
                }
                // ---- 8 MMAs ----
                #pragma unroll
                for (int nt = 0; nt < 4; nt++) {
                    asm volatile("mma.sync.aligned.m16n8k16.row.col.f32.f16.f16.f32 "
                                 "{%0,%1,%2,%3}, {%4,%5,%6,%7}, {%8,%9}, {%0,%1,%2,%3};"
                                 : "+f"(d[0][nt][0]), "+f"(d[0][nt][1]),
                                   "+f"(d[0][nt][2]), "+f"(d[0][nt][3])
                                 : "r"(a0[0]), "r"(a0[1]), "r"(a0[2]), "r"(a0[3]),
                                   "r"(bf[nt][0]), "r"(bf[nt][1]));
                    asm volatile("mma.sync.aligned.m16n8k16.row.col.f32.f16.f16.f32 "
                                 "{%0,%1,%2,%3}, {%4,%5,%6,%7}, {%8,%9}, {%0,%1,%2,%3};"
                                 : "+f"(d[1][nt][0]), "+f"(d[1][nt][1]),
                                   "+f"(d[1][nt][2]), "+f"(d[1][nt][3])
                                 : "r"(a1[0]), "r"(a1[1]), "r"(a1[2]), "r"(a1[3]),
                                   "r"(bf[nt][0]), "r"(bf[nt][1]));
                }
            }
            __syncthreads();
        }

        // ---- epilogue: BN + ReLU + store ----
        const float* ssc = reinterpret_cast<const float*>(smem + OFF_SCALE);
        const float* sbi = reinterpret_cast<const float*>(smem + OFF_BIAS);
        #pragma unroll
        for (int m16 = 0; m16 < 2; m16++) {
            #pragma unroll
            for (int nt = 0; nt < 4; nt++) {
                #pragma unroll
                for (int e = 0; e < 4; e++) {
                    int rloc = m_warp * 32 + m16 * 16 + (lane >> 2) + ((e >> 1) << 3);
                    int c    = n_warp * 32 + nt * 8 + (lane & 3) * 2 + (e & 1);
                    int pp   = tile * 128 + rloc;
                    int r0   = pp / 48;
                    int er   = bh * 48 + r0;
                    int ec   = bw * 48 + (pp - r0 * 48);
                    float v  = fmaxf(fmaf(d[m16][nt][e], ssc[c], sbi[c]), 0.f);
                    out[((size_t)(n * 64 + c) * HH + er) * WW + ec] = v;
                }
            }
        }
    }
}

// ---------------------------------------------------------------------------
extern "C" void kernel_launch(void* const* d_in, const int* in_sizes, int n_in,
                              void* d_out, int out_size) {
    const float* x      = (const float*)d_in[0];
    const float* conv_w = (const float*)d_in[1];
    const float* conv_b = (const float*)d_in[2];
    const float* gamma  = (const float*)d_in[3];
    const float* beta   = (const float*)d_in[4];
    const float* rmean  = (const float*)d_in[5];
    const float* rvar   = (const float*)d_in[6];
    const int*   abi    = (const int*)d_in[7];
    float* out = (float*)d_out;

    int nblk = in_sizes[7] / 3;   // 256

    cudaFuncSetAttribute(conv_kernel,
                         cudaFuncAttributeMaxDynamicSharedMemorySize, SMEM_TOTAL);

    prep_kernel<<<36, 1024>>>(conv_w, conv_b, gamma, beta, rmean, rvar);
    mask_kernel<<<1, 512>>>(abi, nblk);
    zero_kernel<<<dim3(512, 4), 256>>>(out);
    patch_kernel<<<dim3(50, nblk), 256>>>(x, abi);
    conv_kernel<<<dim3(2, nblk), 256, SMEM_TOTAL>>>(abi, out);
}

// round 10
// speedup vs baseline: 5.1525x; 1.4124x over previous
#include <cuda_runtime.h>
#include <cuda_fp16.h>
#include <cstdint>

#define HH      768
#define WW      768
#define BN_EPS  1e-3f

// ---------------- device scratch (no allocations allowed) -------------------
__device__ __half g_patch[256ULL * 50 * 50 * 64];  // [blk][r][c][ci]: 2500 rows x 128B per block
__device__ __half g_wh[9 * 64 * 64];               // [j][co][ci], XOR-swizzled rows
__device__ float  g_scale[64];
__device__ float  g_bias[64];
__device__ int    g_mask[512];

__device__ __forceinline__ uint32_t s2u(const void* p) {
    uint32_t a;
    asm("{ .reg .u64 t; cvta.to.shared.u64 t, %1; cvt.u32.u64 %0, t; }"
        : "=r"(a) : "l"(p));
    return a;
}

// smem map (bytes, dynamic)
#define OFF_SCALE  0
#define OFF_BIAS   256
#define OFF_B      1024            // 9 * 8192 = 73728
#define OFF_A0     74752           // 2 stages x 30208 (236 rows x 128B)
#define ASTAGE     30208
#define SMEM_TOTAL 135168

// ---------------------------------------------------------------------------
// prep: swizzled fp16 weights [j][co][ci], BN folded scale/bias
// ---------------------------------------------------------------------------
__global__ void prep_kernel(const float* __restrict__ w,
                            const float* __restrict__ conv_b,
                            const float* __restrict__ gamma,
                            const float* __restrict__ beta,
                            const float* __restrict__ mean,
                            const float* __restrict__ var) {
    int tid = blockIdx.x * blockDim.x + threadIdx.x;
    for (int i = tid; i < 9 * 64 * 64; i += gridDim.x * blockDim.x) {
        int ci = i & 63, co = (i >> 6) & 63, j = i >> 12;
        int kh = j / 3, kw = j % 3;
        float v = w[((co * 64 + ci) * 3 + kh) * 3 + kw];
        int u  = ci >> 3;
        int su = u ^ (co & 7);               // XOR swizzle within 128B row
        g_wh[j * 4096 + co * 64 + su * 8 + (ci & 7)] = __float2half_rn(v);
    }
    if (tid < 64) {
        float inv = gamma[tid] * rsqrtf(var[tid] + BN_EPS);
        g_scale[tid] = inv;
        g_bias[tid]  = beta[tid] + (conv_b[tid] - mean[tid]) * inv;
    }
}

// ---------------------------------------------------------------------------
__global__ void mask_kernel(const int* __restrict__ abi, int nblk) {
    int t = threadIdx.x;
    if (t < 512) g_mask[t] = 0;
    __syncthreads();
    if (t < nblk) {
        int n = abi[3 * t], bh = abi[3 * t + 1], bw = abi[3 * t + 2];
        g_mask[(n << 8) + (bh << 4) + bw] = 1;
    }
}

// ---------------------------------------------------------------------------
__global__ void zero_kernel(float* __restrict__ out) {
    int blk = blockIdx.x;
    if (g_mask[blk]) return;
    int n = blk >> 8, bh = (blk >> 4) & 15, bw = blk & 15;
    int cbase = blockIdx.y * 16;
    const float4 z = make_float4(0.f, 0.f, 0.f, 0.f);
    for (int i = threadIdx.x; i < 16 * 48 * 12; i += blockDim.x) {
        int q = i % 12, row = (i / 12) % 48, c = cbase + i / (12 * 48);
        float4* p = reinterpret_cast<float4*>(
            out + (((size_t)(n * 64 + c) * HH + bh * 48 + row) * WW + bw * 48)) + q;
        *p = z;
    }
}

// ---------------------------------------------------------------------------
// patch: gather active-block input (with pad-halo) into NHWC fp16 patches.
// Strength-reduced maps: no div/mod in inner loops.
// Phase 1: thread = (col, ci-group), 16 fixed-stride predicated loads.
// Phase 2: s[64][51] padding -> 2-way LDS conflicts only, coalesced STG.
// ---------------------------------------------------------------------------
__global__ __launch_bounds__(256)
void patch_kernel(const float* __restrict__ x, const int* __restrict__ abi) {
    __shared__ __half s[64][51];
    const int r = blockIdx.x, b = blockIdx.y;
    const int n = abi[3 * b], bh = abi[3 * b + 1], bw = abi[3 * b + 2];
    const int gr  = bh * 48 - 1 + r;
    const int gc0 = bw * 48 - 1;
    const bool rok = (unsigned)gr < (unsigned)HH;

    const int c   = threadIdx.x & 63;      // column within patch row
    const int cg  = threadIdx.x >> 6;      // ci group 0..3
    const int gc  = gc0 + c;
    const bool ok = rok && (c < 50) && ((unsigned)gc < (unsigned)WW);

    const float* src = x + ((size_t)(n * 64 + cg * 16) * HH + (rok ? gr : 0)) * WW
                         + (ok ? gc : 0);
    const size_t stride = (size_t)HH * WW;

    if (c < 50) {
        #pragma unroll
        for (int it = 0; it < 16; it++) {
            float v = ok ? __ldg(src) : 0.f;
            s[cg * 16 + it][c] = __float2half_rn(v);
            src += stride;
        }
    }
    __syncthreads();

    // transpose out: coalesced half2 stores
    __half2* dst = reinterpret_cast<__half2*>(g_patch + ((size_t)(b * 50 + r) * 50) * 64);
    const int ci2 = threadIdx.x & 31;
    const int c0  = threadIdx.x >> 5;
    #pragma unroll 2
    for (int cc = c0; cc < 50; cc += 8)
        dst[cc * 32 + ci2] = __halves2half2(s[2 * ci2][cc], s[2 * ci2 + 1][cc]);
}

// ---------------------------------------------------------------------------
// conv: implicit GEMM via mma.sync m16n8k16 fp16.
// CTA = half-block: 9 M-tiles of 128 pos x 64 cout, 8 warps (4m x 2n).
// One contiguous A region (236 rows x 128B) per tile serves ALL 9 j-shifts
// via per-lane ldmatrix addresses in patch-linear space lam(p)=p+2*(p/48).
// Double-buffered across tiles: 2 barriers per tile (18/CTA, was 162).
// ---------------------------------------------------------------------------
__global__ void __launch_bounds__(256, 1)
conv_kernel(const int* __restrict__ abi, float* __restrict__ out) {
    extern __shared__ __align__(1024) char smem[];
    const uint32_t sb = s2u(smem);
    const int tid = threadIdx.x;
    const int b = blockIdx.y;
    const int n = abi[3 * b], bh = abi[3 * b + 1], bw = abi[3 * b + 2];

    // stage all 9 weight chunks (73728 B), layout already swizzled
    {
        const uint4* src = reinterpret_cast<const uint4*>(g_wh);
        uint4* dst = reinterpret_cast<uint4*>(smem + OFF_B);
        #pragma unroll
        for (int i = 0; i < 18; i++) dst[tid + 256 * i] = src[tid + 256 * i];
    }
    if (tid < 64) {
        reinterpret_cast<float*>(smem + OFF_SCALE)[tid] = g_scale[tid];
        reinterpret_cast<float*>(smem + OFF_BIAS)[tid]  = g_bias[tid];
    }

    const int lane = tid & 31;
    const int w    = tid >> 5;
    const int m_warp = w & 3;            // 4 m-warps of 32 rows
    const int n_warp = w >> 2;           // 2 n-warps of 32 cols

    const int a_r  = lane & 15;
    const int a_uh = lane >> 4;
    const int b_n  = (lane & 7) + ((lane >> 4) << 3);
    const int b_uh = (lane >> 3) & 1;

    uint64_t pbase;
    {
        const __half* pb = g_patch + (size_t)b * 2500 * 64;
        asm("cvta.to.global.u64 %0, %1;" : "=l"(pbase) : "l"(pb));
    }
    const int bx9 = blockIdx.x * 9;

    // issue cp.async for one tile's A region into stage (tl&1)
    auto issue_tile = [&](int tl) {
        const int p0 = (bx9 + tl) * 128;
        const int lb = p0 + 2 * (p0 / 48);          // patch-linear base row
        const uint32_t abase = sb + OFF_A0 + (tl & 1) * ASTAGE;
        #pragma unroll
        for (int it = 0; it < 8; it++) {
            int i = tid + it * 256;                  // 236*8 = 1888 units
            if (i < 1888) {
                int lam = i >> 3, u = i & 7;
                int lsrc = lb + lam;
                if (lsrc > 2499) lsrc = 2499;        // clamp (rows unused by gemm)
                uint32_t dst = abase + (uint32_t)(lam * 128 + ((u ^ (lam & 7)) * 16));
                uint64_t src = pbase + (uint64_t)lsrc * 128 + (uint64_t)u * 16;
                asm volatile("cp.async.cg.shared.global [%0], [%1], 16;"
                             :: "r"(dst), "l"(src) : "memory");
            }
        }
        asm volatile("cp.async.commit_group;" ::: "memory");
    };

    issue_tile(0);   // prologue

    const float* ssc = reinterpret_cast<const float*>(smem + OFF_SCALE);
    const float* sbi = reinterpret_cast<const float*>(smem + OFF_BIAS);

    for (int tl = 0; tl < 9; tl++) {
        asm volatile("cp.async.wait_group 0;" ::: "memory");
        __syncthreads();
        if (tl < 8) issue_tile(tl + 1);   // overlaps with this tile's gemm

        const int tile = bx9 + tl;
        const int p0 = tile * 128;
        const int l0 = p0 + 2 * (p0 / 48);
        const int pf0 = p0 + m_warp * 32 + a_r;
        const int lb0 = pf0 + 2 * (pf0 / 48) - l0;   // lane's linear row, m16 tile 0
        const int pf1 = pf0 + 16;
        const int lb1 = pf1 + 2 * (pf1 / 48) - l0;   // m16 tile 1
        const uint32_t abase = sb + OFF_A0 + (tl & 1) * ASTAGE;

        float d[2][4][4];
        #pragma unroll
        for (int a = 0; a < 2; a++)
            #pragma unroll
            for (int cq = 0; cq < 4; cq++)
                #pragma unroll
                for (int e = 0; e < 4; e++) d[a][cq][e] = 0.f;

        #pragma unroll
        for (int j = 0; j < 9; j++) {
            const int joff = (j / 3) * 50 + (j % 3);
            const int la0 = lb0 + joff;
            const int la1 = lb1 + joff;
            const uint32_t r0base = abase + (uint32_t)(la0 * 128);
            const uint32_t r1base = abase + (uint32_t)(la1 * 128);
            const uint32_t sw0 = (uint32_t)((la0 & 7) * 16);
            const uint32_t sw1 = (uint32_t)((la1 & 7) * 16);
            const uint32_t bbase = sb + OFF_B + j * 8192;

            #pragma unroll
            for (int ks = 0; ks < 4; ks++) {
                uint32_t a0[4], a1[4];
                {
                    uint32_t addr = r0base + ((uint32_t)((ks * 2 + a_uh) * 16) ^ sw0);
                    asm volatile("ldmatrix.sync.aligned.m8n8.x4.shared.b16 "
                                 "{%0,%1,%2,%3}, [%4];"
                                 : "=r"(a0[0]), "=r"(a0[1]), "=r"(a0[2]), "=r"(a0[3])
                                 : "r"(addr));
                    addr = r1base + ((uint32_t)((ks * 2 + a_uh) * 16) ^ sw1);
                    asm volatile("ldmatrix.sync.aligned.m8n8.x4.shared.b16 "
                                 "{%0,%1,%2,%3}, [%4];"
                                 : "=r"(a1[0]), "=r"(a1[1]), "=r"(a1[2]), "=r"(a1[3])
                                 : "r"(addr));
                }
                uint32_t bf[4][2];
                {
                    int nn = n_warp * 32 + b_n;
                    uint32_t addr = bbase + (uint32_t)(nn * 128 +
                                    (((ks * 2 + b_uh) ^ (nn & 7)) * 16));
                    asm volatile("ldmatrix.sync.aligned.m8n8.x4.shared.b16 "
                                 "{%0,%1,%2,%3}, [%4];"
                                 : "=r"(bf[0][0]), "=r"(bf[0][1]),
                                   "=r"(bf[1][0]), "=r"(bf[1][1])
                                 : "r"(addr));
                    nn += 16;
                    addr = bbase + (uint32_t)(nn * 128 +
                           (((ks * 2 + b_uh) ^ (nn & 7)) * 16));
                    asm volatile("ldmatrix.sync.aligned.m8n8.x4.shared.b16 "
                                 "{%0,%1,%2,%3}, [%4];"
                                 : "=r"(bf[2][0]), "=r"(bf[2][1]),
                                   "=r"(bf[3][0]), "=r"(bf[3][1])
                                 : "r"(addr));
                }
                #pragma unroll
                for (int nt = 0; nt < 4; nt++) {
                    asm volatile("mma.sync.aligned.m16n8k16.row.col.f32.f16.f16.f32 "
                                 "{%0,%1,%2,%3}, {%4,%5,%6,%7}, {%8,%9}, {%0,%1,%2,%3};"
                                 : "+f"(d[0][nt][0]), "+f"(d[0][nt][1]),
                                   "+f"(d[0][nt][2]), "+f"(d[0][nt][3])
                                 : "r"(a0[0]), "r"(a0[1]), "r"(a0[2]), "r"(a0[3]),
                                   "r"(bf[nt][0]), "r"(bf[nt][1]));
                    asm volatile("mma.sync.aligned.m16n8k16.row.col.f32.f16.f16.f32 "
                                 "{%0,%1,%2,%3}, {%4,%5,%6,%7}, {%8,%9}, {%0,%1,%2,%3};"
                                 : "+f"(d[1][nt][0]), "+f"(d[1][nt][1]),
                                   "+f"(d[1][nt][2]), "+f"(d[1][nt][3])
                                 : "r"(a1[0]), "r"(a1[1]), "r"(a1[2]), "r"(a1[3]),
                                   "r"(bf[nt][0]), "r"(bf[nt][1]));
                }
            }
        }

        // ---- epilogue: BN + ReLU + store (overlaps with next tile's cp.async) ----
        #pragma unroll
        for (int m16 = 0; m16 < 2; m16++) {
            #pragma unroll
            for (int nt = 0; nt < 4; nt++) {
                #pragma unroll
                for (int e = 0; e < 4; e++) {
                    int rloc = m_warp * 32 + m16 * 16 + (lane >> 2) + ((e >> 1) << 3);
                    int c    = n_warp * 32 + nt * 8 + (lane & 3) * 2 + (e & 1);
                    int pp   = tile * 128 + rloc;
                    int r0   = pp / 48;
                    int er   = bh * 48 + r0;
                    int ec   = bw * 48 + (pp - r0 * 48);
                    float v  = fmaxf(fmaf(d[m16][nt][e], ssc[c], sbi[c]), 0.f);
                    out[((size_t)(n * 64 + c) * HH + er) * WW + ec] = v;
                }
            }
        }
    }
}

// ---------------------------------------------------------------------------
extern "C" void kernel_launch(void* const* d_in, const int* in_sizes, int n_in,
                              void* d_out, int out_size) {
    const float* x      = (const float*)d_in[0];
    const float* conv_w = (const float*)d_in[1];
    const float* conv_b = (const float*)d_in[2];
    const float* gamma  = (const float*)d_in[3];
    const float* beta   = (const float*)d_in[4];
    const float* rmean  = (const float*)d_in[5];
    const float* rvar   = (const float*)d_in[6];
    const int*   abi    = (const int*)d_in[7];
    float* out = (float*)d_out;

    int nblk = in_sizes[7] / 3;   // 256

    cudaFuncSetAttribute(conv_kernel,
                         cudaFuncAttributeMaxDynamicSharedMemorySize, SMEM_TOTAL);

    prep_kernel<<<36, 1024>>>(conv_w, conv_b, gamma, beta, rmean, rvar);
    mask_kernel<<<1, 512>>>(abi, nblk);
    zero_kernel<<<dim3(512, 4), 256>>>(out);
    patch_kernel<<<dim3(50, nblk), 256>>>(x, abi);
    conv_kernel<<<dim3(2, nblk), 256, SMEM_TOTAL>>>(abi, out);
}

// round 11
// speedup vs baseline: 5.4999x; 1.0674x over previous
#include <cuda_runtime.h>
#include <cuda_fp16.h>
#include <cstdint>

#define HH      768
#define WW      768
#define BN_EPS  1e-3f

// ---------------- device scratch (no allocations allowed) -------------------
__device__ __half g_patch[256ULL * 50 * 50 * 64];  // [blk][r][c][ci]: 2500 rows x 128B per block
__device__ __half g_wh[9 * 64 * 64];               // [j][co][ci], XOR-swizzled rows
__device__ float  g_scale[64];
__device__ float  g_bias[64];
__device__ int    g_mask[512];

__device__ __forceinline__ uint32_t s2u(const void* p) {
    uint32_t a;
    asm("{ .reg .u64 t; cvta.to.shared.u64 t, %1; cvt.u32.u64 %0, t; }"
        : "=r"(a) : "l"(p));
    return a;
}

// smem map (bytes, dynamic)
#define OFF_SCALE  0
#define OFF_BIAS   256
#define OFF_B      1024            // 9 * 8192 = 73728
#define OFF_A0     74752           // 2 stages x 47616 (372 rows x 128B)
#define ASTAGE     47616
#define SMEM_TOTAL 169984

// ---------------------------------------------------------------------------
// prep: swizzled fp16 weights [j][co][ci], BN folded scale/bias
// ---------------------------------------------------------------------------
__global__ void prep_kernel(const float* __restrict__ w,
                            const float* __restrict__ conv_b,
                            const float* __restrict__ gamma,
                            const float* __restrict__ beta,
                            const float* __restrict__ mean,
                            const float* __restrict__ var) {
    int tid = blockIdx.x * blockDim.x + threadIdx.x;
    for (int i = tid; i < 9 * 64 * 64; i += gridDim.x * blockDim.x) {
        int ci = i & 63, co = (i >> 6) & 63, j = i >> 12;
        int kh = j / 3, kw = j % 3;
        float v = w[((co * 64 + ci) * 3 + kh) * 3 + kw];
        int u  = ci >> 3;
        int su = u ^ (co & 7);               // XOR swizzle within 128B row
        g_wh[j * 4096 + co * 64 + su * 8 + (ci & 7)] = __float2half_rn(v);
    }
    if (tid < 64) {
        float inv = gamma[tid] * rsqrtf(var[tid] + BN_EPS);
        g_scale[tid] = inv;
        g_bias[tid]  = beta[tid] + (conv_b[tid] - mean[tid]) * inv;
    }
}

// ---------------------------------------------------------------------------
__global__ void mask_kernel(const int* __restrict__ abi, int nblk) {
    int t = threadIdx.x;
    if (t < 512) g_mask[t] = 0;
    __syncthreads();
    if (t < nblk) {
        int n = abi[3 * t], bh = abi[3 * t + 1], bw = abi[3 * t + 2];
        g_mask[(n << 8) + (bh << 4) + bw] = 1;
    }
}

// ---------------------------------------------------------------------------
__global__ void zero_kernel(float* __restrict__ out) {
    int blk = blockIdx.x;
    if (g_mask[blk]) return;
    int n = blk >> 8, bh = (blk >> 4) & 15, bw = blk & 15;
    int cbase = blockIdx.y * 16;
    const float4 z = make_float4(0.f, 0.f, 0.f, 0.f);
    for (int i = threadIdx.x; i < 16 * 48 * 12; i += blockDim.x) {
        int q = i % 12, row = (i / 12) % 48, c = cbase + i / (12 * 48);
        float4* p = reinterpret_cast<float4*>(
            out + (((size_t)(n * 64 + c) * HH + bh * 48 + row) * WW + bw * 48)) + q;
        *p = z;
    }
}

// ---------------------------------------------------------------------------
// patch: gather active-block input (with pad-halo) into NHWC fp16 patches.
// ---------------------------------------------------------------------------
__global__ __launch_bounds__(256)
void patch_kernel(const float* __restrict__ x, const int* __restrict__ abi) {
    __shared__ __half s[64][51];
    const int r = blockIdx.x, b = blockIdx.y;
    const int n = abi[3 * b], bh = abi[3 * b + 1], bw = abi[3 * b + 2];
    const int gr  = bh * 48 - 1 + r;
    const int gc0 = bw * 48 - 1;
    const bool rok = (unsigned)gr < (unsigned)HH;

    const int c   = threadIdx.x & 63;
    const int cg  = threadIdx.x >> 6;
    const int gc  = gc0 + c;
    const bool ok = rok && (c < 50) && ((unsigned)gc < (unsigned)WW);

    const float* src = x + ((size_t)(n * 64 + cg * 16) * HH + (rok ? gr : 0)) * WW
                         + (ok ? gc : 0);
    const size_t stride = (size_t)HH * WW;

    if (c < 50) {
        #pragma unroll
        for (int it = 0; it < 16; it++) {
            float v = ok ? __ldg(src) : 0.f;
            s[cg * 16 + it][c] = __float2half_rn(v);
            src += stride;
        }
    }
    __syncthreads();

    __half2* dst = reinterpret_cast<__half2*>(g_patch + ((size_t)(b * 50 + r) * 50) * 64);
    const int ci2 = threadIdx.x & 31;
    const int c0  = threadIdx.x >> 5;
    #pragma unroll 2
    for (int cc = c0; cc < 50; cc += 8)
        dst[cc * 32 + ci2] = __halves2half2(s[2 * ci2][cc], s[2 * ci2 + 1][cc]);
}

// ---------------------------------------------------------------------------
// conv: implicit GEMM via mma.sync m16n8k16 fp16.
// CTA = ONE block: 9 M-tiles of 256 pos x 64 cout, 512 threads,
// 16 warps (8 m-warps x 2 n-warps), warp tile 32x32. 4 warps/SMSP for
// latency hiding. One contiguous A region (372 rows x 128B) per tile serves
// all 9 j-shifts via per-lane patch-linear addressing lam(p)=p+2*(p/48);
// double-buffered across tiles.
// ---------------------------------------------------------------------------
__global__ void __launch_bounds__(512, 1)
conv_kernel(const int* __restrict__ abi, float* __restrict__ out) {
    extern __shared__ __align__(1024) char smem[];
    const uint32_t sb = s2u(smem);
    const int tid = threadIdx.x;
    const int b = blockIdx.x;
    const int n = abi[3 * b], bh = abi[3 * b + 1], bw = abi[3 * b + 2];

    // stage all 9 weight chunks (73728 B = 4608 uint4)
    {
        const uint4* src = reinterpret_cast<const uint4*>(g_wh);
        uint4* dst = reinterpret_cast<uint4*>(smem + OFF_B);
        #pragma unroll
        for (int i = 0; i < 9; i++) dst[tid + 512 * i] = src[tid + 512 * i];
    }
    if (tid < 64) {
        reinterpret_cast<float*>(smem + OFF_SCALE)[tid] = g_scale[tid];
        reinterpret_cast<float*>(smem + OFF_BIAS)[tid]  = g_bias[tid];
    }

    const int lane = tid & 31;
    const int w    = tid >> 5;
    const int m_warp = w & 7;            // 8 m-warps of 32 rows
    const int n_warp = w >> 3;           // 2 n-warps of 32 cols

    const int a_r  = lane & 15;
    const int a_uh = lane >> 4;
    const int b_n  = (lane & 7) + ((lane >> 4) << 3);
    const int b_uh = (lane >> 3) & 1;

    uint64_t pbase;
    {
        const __half* pb = g_patch + (size_t)b * 2500 * 64;
        asm("cvta.to.global.u64 %0, %1;" : "=l"(pbase) : "l"(pb));
    }

    // issue cp.async for one tile's A region (372 rows) into stage (tl&1)
    auto issue_tile = [&](int tl) {
        const int p0 = tl * 256;
        const int lb = p0 + 2 * (p0 / 48);          // patch-linear base row
        const uint32_t abase = sb + OFF_A0 + (tl & 1) * ASTAGE;
        #pragma unroll
        for (int it = 0; it < 6; it++) {
            int i = tid + it * 512;                  // 372*8 = 2976 units
            if (i < 2976) {
                int lam = i >> 3, u = i & 7;
                int lsrc = lb + lam;
                if (lsrc > 2499) lsrc = 2499;        // clamp (rows unused by gemm)
                uint32_t dst = abase + (uint32_t)(lam * 128 + ((u ^ (lam & 7)) * 16));
                uint64_t src = pbase + (uint64_t)lsrc * 128 + (uint64_t)u * 16;
                asm volatile("cp.async.cg.shared.global [%0], [%1], 16;"
                             :: "r"(dst), "l"(src) : "memory");
            }
        }
        asm volatile("cp.async.commit_group;" ::: "memory");
    };

    issue_tile(0);   // prologue

    const float* ssc = reinterpret_cast<const float*>(smem + OFF_SCALE);
    const float* sbi = reinterpret_cast<const float*>(smem + OFF_BIAS);

    for (int tl = 0; tl < 9; tl++) {
        asm volatile("cp.async.wait_group 0;" ::: "memory");
        __syncthreads();
        if (tl < 8) issue_tile(tl + 1);   // overlaps with this tile's gemm

        const int p0 = tl * 256;
        const int l0 = p0 + 2 * (p0 / 48);
        const int pf0 = p0 + m_warp * 32 + a_r;
        const int lb0 = pf0 + 2 * (pf0 / 48) - l0;   // lane's linear row, m16 tile 0
        const int pf1 = pf0 + 16;
        const int lb1 = pf1 + 2 * (pf1 / 48) - l0;   // m16 tile 1
        const uint32_t abase = sb + OFF_A0 + (tl & 1) * ASTAGE;

        float d[2][4][4];
        #pragma unroll
        for (int a = 0; a < 2; a++)
            #pragma unroll
            for (int cq = 0; cq < 4; cq++)
                #pragma unroll
                for (int e = 0; e < 4; e++) d[a][cq][e] = 0.f;

        #pragma unroll
        for (int j = 0; j < 9; j++) {
            const int joff = (j / 3) * 50 + (j % 3);
            const int la0 = lb0 + joff;
            const int la1 = lb1 + joff;
            const uint32_t r0base = abase + (uint32_t)(la0 * 128);
            const uint32_t r1base = abase + (uint32_t)(la1 * 128);
            const uint32_t sw0 = (uint32_t)((la0 & 7) * 16);
            const uint32_t sw1 = (uint32_t)((la1 & 7) * 16);
            const uint32_t bbase = sb + OFF_B + j * 8192;

            #pragma unroll
            for (int ks = 0; ks < 4; ks++) {
                uint32_t a0[4], a1[4];
                {
                    uint32_t addr = r0base + ((uint32_t)((ks * 2 + a_uh) * 16) ^ sw0);
                    asm volatile("ldmatrix.sync.aligned.m8n8.x4.shared.b16 "
                                 "{%0,%1,%2,%3}, [%4];"
                                 : "=r"(a0[0]), "=r"(a0[1]), "=r"(a0[2]), "=r"(a0[3])
                                 : "r"(addr));
                    addr = r1base + ((uint32_t)((ks * 2 + a_uh) * 16) ^ sw1);
                    asm volatile("ldmatrix.sync.aligned.m8n8.x4.shared.b16 "
                                 "{%0,%1,%2,%3}, [%4];"
                                 : "=r"(a1[0]), "=r"(a1[1]), "=r"(a1[2]), "=r"(a1[3])
                                 : "r"(addr));
                }
                uint32_t bf[4][2];
                {
                    int nn = n_warp * 32 + b_n;
                    uint32_t addr = bbase + (uint32_t)(nn * 128 +
                                    (((ks * 2 + b_uh) ^ (nn & 7)) * 16));
                    asm volatile("ldmatrix.sync.aligned.m8n8.x4.shared.b16 "
                                 "{%0,%1,%2,%3}, [%4];"
                                 : "=r"(bf[0][0]), "=r"(bf[0][1]),
                                   "=r"(bf[1][0]), "=r"(bf[1][1])
                                 : "r"(addr));
                    nn += 16;
                    addr = bbase + (uint32_t)(nn * 128 +
                           (((ks * 2 + b_uh) ^ (nn & 7)) * 16));
                    asm volatile("ldmatrix.sync.aligned.m8n8.x4.shared.b16 "
                                 "{%0,%1,%2,%3}, [%4];"
                                 : "=r"(bf[2][0]), "=r"(bf[2][1]),
                                   "=r"(bf[3][0]), "=r"(bf[3][1])
                                 : "r"(addr));
                }
                #pragma unroll
                for (int nt = 0; nt < 4; nt++) {
                    asm volatile("mma.sync.aligned.m16n8k16.row.col.f32.f16.f16.f32 "
                                 "{%0,%1,%2,%3}, {%4,%5,%6,%7}, {%8,%9}, {%0,%1,%2,%3};"
                                 : "+f"(d[0][nt][0]), "+f"(d[0][nt][1]),
                                   "+f"(d[0][nt][2]), "+f"(d[0][nt][3])
                                 : "r"(a0[0]), "r"(a0[1]), "r"(a0[2]), "r"(a0[3]),
                                   "r"(bf[nt][0]), "r"(bf[nt][1]));
                    asm volatile("mma.sync.aligned.m16n8k16.row.col.f32.f16.f16.f32 "
                                 "{%0,%1,%2,%3}, {%4,%5,%6,%7}, {%8,%9}, {%0,%1,%2,%3};"
                                 : "+f"(d[1][nt][0]), "+f"(d[1][nt][1]),
                                   "+f"(d[1][nt][2]), "+f"(d[1][nt][3])
                                 : "r"(a1[0]), "r"(a1[1]), "r"(a1[2]), "r"(a1[3]),
                                   "r"(bf[nt][0]), "r"(bf[nt][1]));
                }
            }
        }

        // ---- epilogue: BN + ReLU + store (overlaps with next tile's cp.async) ----
        #pragma unroll
        for (int m16 = 0; m16 < 2; m16++) {
            #pragma unroll
            for (int nt = 0; nt < 4; nt++) {
                #pragma unroll
                for (int e = 0; e < 4; e++) {
                    int rloc = m_warp * 32 + m16 * 16 + (lane >> 2) + ((e >> 1) << 3);
                    int c    = n_warp * 32 + nt * 8 + (lane & 3) * 2 + (e & 1);
                    int pp   = p0 + rloc;
                    int r0   = pp / 48;
                    int er   = bh * 48 + r0;
                    int ec   = bw * 48 + (pp - r0 * 48);
                    float v  = fmaxf(fmaf(d[m16][nt][e], ssc[c], sbi[c]), 0.f);
                    out[((size_t)(n * 64 + c) * HH + er) * WW + ec] = v;
                }
            }
        }
    }
}

// ---------------------------------------------------------------------------
extern "C" void kernel_launch(void* const* d_in, const int* in_sizes, int n_in,
                              void* d_out, int out_size) {
    const float* x      = (const float*)d_in[0];
    const float* conv_w = (const float*)d_in[1];
    const float* conv_b = (const float*)d_in[2];
    const float* gamma  = (const float*)d_in[3];
    const float* beta   = (const float*)d_in[4];
    const float* rmean  = (const float*)d_in[5];
    const float* rvar   = (const float*)d_in[6];
    const int*   abi    = (const int*)d_in[7];
    float* out = (float*)d_out;

    int nblk = in_sizes[7] / 3;   // 256

    cudaFuncSetAttribute(conv_kernel,
                         cudaFuncAttributeMaxDynamicSharedMemorySize, SMEM_TOTAL);

    prep_kernel<<<36, 1024>>>(conv_w, conv_b, gamma, beta, rmean, rvar);
    mask_kernel<<<1, 512>>>(abi, nblk);
    zero_kernel<<<dim3(512, 4), 256>>>(out);
    patch_kernel<<<dim3(50, nblk), 256>>>(x, abi);
    conv_kernel<<<nblk, 512, SMEM_TOTAL>>>(abi, out);
}

// round 12
// speedup vs baseline: 6.2863x; 1.1430x over previous
#include <cuda_runtime.h>
#include <cuda_fp16.h>
#include <cstdint>

#define HH      768
#define WW      768
#define BN_EPS  1e-3f

// ---------------- device scratch (no allocations allowed) -------------------
__device__ __half g_patch[256ULL * 50 * 50 * 64];  // [blk][r][c][ci]: 2500 rows x 128B per block
__device__ __half g_wh[9 * 64 * 64];               // [j][co][ci], XOR-swizzled rows
__device__ float  g_scale[64];
__device__ float  g_bias[64];
__device__ int    g_mask[512];
__device__ int    g_inact[512];
__device__ int    g_ninact;

__device__ __forceinline__ uint32_t s2u(const void* p) {
    uint32_t a;
    asm("{ .reg .u64 t; cvta.to.shared.u64 t, %1; cvt.u32.u64 %0, t; }"
        : "=r"(a) : "l"(p));
    return a;
}

// smem map (bytes, dynamic)
#define OFF_SCALE  0
#define OFF_BIAS   256
#define OFF_B      1024            // 9 * 8192 = 73728
#define OFF_A0     74752           // 2 stages x 47616 (372 rows x 128B)
#define ASTAGE     47616
#define SMEM_TOTAL 169984

// ---------------------------------------------------------------------------
// prep: swizzled fp16 weights [j][co][ci], BN folded scale/bias
// ---------------------------------------------------------------------------
__global__ void prep_kernel(const float* __restrict__ w,
                            const float* __restrict__ conv_b,
                            const float* __restrict__ gamma,
                            const float* __restrict__ beta,
                            const float* __restrict__ mean,
                            const float* __restrict__ var) {
    int tid = blockIdx.x * blockDim.x + threadIdx.x;
    for (int i = tid; i < 9 * 64 * 64; i += gridDim.x * blockDim.x) {
        int ci = i & 63, co = (i >> 6) & 63, j = i >> 12;
        int kh = j / 3, kw = j % 3;
        float v = w[((co * 64 + ci) * 3 + kh) * 3 + kw];
        int u  = ci >> 3;
        int su = u ^ (co & 7);               // XOR swizzle within 128B row
        g_wh[j * 4096 + co * 64 + su * 8 + (ci & 7)] = __float2half_rn(v);
    }
    if (tid < 64) {
        float inv = gamma[tid] * rsqrtf(var[tid] + BN_EPS);
        g_scale[tid] = inv;
        g_bias[tid]  = beta[tid] + (conv_b[tid] - mean[tid]) * inv;
    }
}

// ---------------------------------------------------------------------------
// mask: mark active blocks, then build the inactive-block list
// ---------------------------------------------------------------------------
__global__ void mask_kernel(const int* __restrict__ abi, int nblk) {
    int t = threadIdx.x;
    if (t == 0) g_ninact = 0;
    if (t < 512) g_mask[t] = 0;
    __syncthreads();
    if (t < nblk) {
        int n = abi[3 * t], bh = abi[3 * t + 1], bw = abi[3 * t + 2];
        g_mask[(n << 8) + (bh << 4) + bw] = 1;
    }
    __syncthreads();
    if (t < 512 && !g_mask[t]) {
        int pos = atomicAdd(&g_ninact, 1);
        g_inact[pos] = t;
    }
}

// ---------------------------------------------------------------------------
// patch: gather active-block input (with pad-halo) into NHWC fp16 patches.
// ---------------------------------------------------------------------------
__global__ __launch_bounds__(256)
void patch_kernel(const float* __restrict__ x, const int* __restrict__ abi) {
    __shared__ __half s[64][51];
    const int r = blockIdx.x, b = blockIdx.y;
    const int n = abi[3 * b], bh = abi[3 * b + 1], bw = abi[3 * b + 2];
    const int gr  = bh * 48 - 1 + r;
    const int gc0 = bw * 48 - 1;
    const bool rok = (unsigned)gr < (unsigned)HH;

    const int c   = threadIdx.x & 63;
    const int cg  = threadIdx.x >> 6;
    const int gc  = gc0 + c;
    const bool ok = rok && (c < 50) && ((unsigned)gc < (unsigned)WW);

    const float* src = x + ((size_t)(n * 64 + cg * 16) * HH + (rok ? gr : 0)) * WW
                         + (ok ? gc : 0);
    const size_t stride = (size_t)HH * WW;

    if (c < 50) {
        #pragma unroll
        for (int it = 0; it < 16; it++) {
            float v = ok ? __ldg(src) : 0.f;
            s[cg * 16 + it][c] = __float2half_rn(v);
            src += stride;
        }
    }
    __syncthreads();

    __half2* dst = reinterpret_cast<__half2*>(g_patch + ((size_t)(b * 50 + r) * 50) * 64);
    const int ci2 = threadIdx.x & 31;
    const int c0  = threadIdx.x >> 5;
    #pragma unroll 2
    for (int cc = c0; cc < 50; cc += 8)
        dst[cc * 32 + ci2] = __halves2half2(s[2 * ci2][cc], s[2 * ci2 + 1][cc]);
}

// ---------------------------------------------------------------------------
// conv: implicit GEMM via mma.sync m16n8k16 fp16, PLUS fused zeroing.
// CTAs [0, nblk): one active block each (9 M-tiles of 256 pos x 64 cout),
// 512 threads = 16 warps (8m x 2n), warp tile 32x32.
// CTAs [nblk, nblk+ninact): zero one inactive 48x48x64 output region each
// (cheap; backfills wave-2 SM idle time).
// ---------------------------------------------------------------------------
__global__ void __launch_bounds__(512, 1)
conv_kernel(const int* __restrict__ abi, float* __restrict__ out, int nblk) {
    const int tid = threadIdx.x;
    const int b = blockIdx.x;

    // ---- zero branch: inactive blocks ----
    if (b >= nblk) {
        int k = b - nblk;
        if (k < g_ninact) {
            int blk = g_inact[k];
            int zn = blk >> 8, zbh = (blk >> 4) & 15, zbw = blk & 15;
            const float4 z = make_float4(0.f, 0.f, 0.f, 0.f);
            // 64 ch * 48 rows * 12 float4 = 36864
            for (int i = tid; i < 36864; i += 512) {
                int q = i % 12, row = (i / 12) % 48, c = i / (12 * 48);
                float4* p = reinterpret_cast<float4*>(
                    out + (((size_t)(zn * 64 + c) * HH + zbh * 48 + row) * WW
                           + zbw * 48)) + q;
                *p = z;
            }
        }
        return;
    }

    extern __shared__ __align__(1024) char smem[];
    const uint32_t sb = s2u(smem);
    const int n = abi[3 * b], bh = abi[3 * b + 1], bw = abi[3 * b + 2];

    // stage all 9 weight chunks (73728 B = 4608 uint4)
    {
        const uint4* src = reinterpret_cast<const uint4*>(g_wh);
        uint4* dst = reinterpret_cast<uint4*>(smem + OFF_B);
        #pragma unroll
        for (int i = 0; i < 9; i++) dst[tid + 512 * i] = src[tid + 512 * i];
    }
    if (tid < 64) {
        reinterpret_cast<float*>(smem + OFF_SCALE)[tid] = g_scale[tid];
        reinterpret_cast<float*>(smem + OFF_BIAS)[tid]  = g_bias[tid];
    }

    const int lane = tid & 31;
    const int w    = tid >> 5;
    const int m_warp = w & 7;            // 8 m-warps of 32 rows
    const int n_warp = w >> 3;           // 2 n-warps of 32 cols

    const int a_r  = lane & 15;
    const int a_uh = lane >> 4;
    const int b_n  = (lane & 7) + ((lane >> 4) << 3);
    const int b_uh = (lane >> 3) & 1;

    uint64_t pbase;
    {
        const __half* pb = g_patch + (size_t)b * 2500 * 64;
        asm("cvta.to.global.u64 %0, %1;" : "=l"(pbase) : "l"(pb));
    }

    // issue cp.async for one tile's A region (372 rows) into stage (tl&1)
    auto issue_tile = [&](int tl) {
        const int p0 = tl * 256;
        const int lb = p0 + 2 * (p0 / 48);          // patch-linear base row
        const uint32_t abase = sb + OFF_A0 + (tl & 1) * ASTAGE;
        #pragma unroll
        for (int it = 0; it < 6; it++) {
            int i = tid + it * 512;                  // 372*8 = 2976 units
            if (i < 2976) {
                int lam = i >> 3, u = i & 7;
                int lsrc = lb + lam;
                if (lsrc > 2499) lsrc = 2499;        // clamp (rows unused by gemm)
                uint32_t dst = abase + (uint32_t)(lam * 128 + ((u ^ (lam & 7)) * 16));
                uint64_t src = pbase + (uint64_t)lsrc * 128 + (uint64_t)u * 16;
                asm volatile("cp.async.cg.shared.global [%0], [%1], 16;"
                             :: "r"(dst), "l"(src) : "memory");
            }
        }
        asm volatile("cp.async.commit_group;" ::: "memory");
    };

    issue_tile(0);   // prologue

    const float* ssc = reinterpret_cast<const float*>(smem + OFF_SCALE);
    const float* sbi = reinterpret_cast<const float*>(smem + OFF_BIAS);

    for (int tl = 0; tl < 9; tl++) {
        asm volatile("cp.async.wait_group 0;" ::: "memory");
        __syncthreads();
        if (tl < 8) issue_tile(tl + 1);   // overlaps with this tile's gemm

        const int p0 = tl * 256;
        const int l0 = p0 + 2 * (p0 / 48);
        const int pf0 = p0 + m_warp * 32 + a_r;
        const int lb0 = pf0 + 2 * (pf0 / 48) - l0;   // lane's linear row, m16 tile 0
        const int pf1 = pf0 + 16;
        const int lb1 = pf1 + 2 * (pf1 / 48) - l0;   // m16 tile 1
        const uint32_t abase = sb + OFF_A0 + (tl & 1) * ASTAGE;

        float d[2][4][4];
        #pragma unroll
        for (int a = 0; a < 2; a++)
            #pragma unroll
            for (int cq = 0; cq < 4; cq++)
                #pragma unroll
                for (int e = 0; e < 4; e++) d[a][cq][e] = 0.f;

        #pragma unroll
        for (int j = 0; j < 9; j++) {
            const int joff = (j / 3) * 50 + (j % 3);
            const int la0 = lb0 + joff;
            const int la1 = lb1 + joff;
            const uint32_t r0base = abase + (uint32_t)(la0 * 128);
            const uint32_t r1base = abase + (uint32_t)(la1 * 128);
            const uint32_t sw0 = (uint32_t)((la0 & 7) * 16);
            const uint32_t sw1 = (uint32_t)((la1 & 7) * 16);
            const uint32_t bbase = sb + OFF_B + j * 8192;

            #pragma unroll
            for (int ks = 0; ks < 4; ks++) {
                uint32_t a0[4], a1[4];
                {
                    uint32_t addr = r0base + ((uint32_t)((ks * 2 + a_uh) * 16) ^ sw0);
                    asm volatile("ldmatrix.sync.aligned.m8n8.x4.shared.b16 "
                                 "{%0,%1,%2,%3}, [%4];"
                                 : "=r"(a0[0]), "=r"(a0[1]), "=r"(a0[2]), "=r"(a0[3])
                                 : "r"(addr));
                    addr = r1base + ((uint32_t)((ks * 2 + a_uh) * 16) ^ sw1);
                    asm volatile("ldmatrix.sync.aligned.m8n8.x4.shared.b16 "
                                 "{%0,%1,%2,%3}, [%4];"
                                 : "=r"(a1[0]), "=r"(a1[1]), "=r"(a1[2]), "=r"(a1[3])
                                 : "r"(addr));
                }
                uint32_t bf[4][2];
                {
                    int nn = n_warp * 32 + b_n;
                    uint32_t addr = bbase + (uint32_t)(nn * 128 +
                                    (((ks * 2 + b_uh) ^ (nn & 7)) * 16));
                    asm volatile("ldmatrix.sync.aligned.m8n8.x4.shared.b16 "
                                 "{%0,%1,%2,%3}, [%4];"
                                 : "=r"(bf[0][0]), "=r"(bf[0][1]),
                                   "=r"(bf[1][0]), "=r"(bf[1][1])
                                 : "r"(addr));
                    nn += 16;
                    addr = bbase + (uint32_t)(nn * 128 +
                           (((ks * 2 + b_uh) ^ (nn & 7)) * 16));
                    asm volatile("ldmatrix.sync.aligned.m8n8.x4.shared.b16 "
                                 "{%0,%1,%2,%3}, [%4];"
                                 : "=r"(bf[2][0]), "=r"(bf[2][1]),
                                   "=r"(bf[3][0]), "=r"(bf[3][1])
                                 : "r"(addr));
                }
                #pragma unroll
                for (int nt = 0; nt < 4; nt++) {
                    asm volatile("mma.sync.aligned.m16n8k16.row.col.f32.f16.f16.f32 "
                                 "{%0,%1,%2,%3}, {%4,%5,%6,%7}, {%8,%9}, {%0,%1,%2,%3};"
                                 : "+f"(d[0][nt][0]), "+f"(d[0][nt][1]),
                                   "+f"(d[0][nt][2]), "+f"(d[0][nt][3])
                                 : "r"(a0[0]), "r"(a0[1]), "r"(a0[2]), "r"(a0[3]),
                                   "r"(bf[nt][0]), "r"(bf[nt][1]));
                    asm volatile("mma.sync.aligned.m16n8k16.row.col.f32.f16.f16.f32 "
                                 "{%0,%1,%2,%3}, {%4,%5,%6,%7}, {%8,%9}, {%0,%1,%2,%3};"
                                 : "+f"(d[1][nt][0]), "+f"(d[1][nt][1]),
                                   "+f"(d[1][nt][2]), "+f"(d[1][nt][3])
                                 : "r"(a1[0]), "r"(a1[1]), "r"(a1[2]), "r"(a1[3]),
                                   "r"(bf[nt][0]), "r"(bf[nt][1]));
                }
            }
        }

        // ---- epilogue: BN + ReLU + store (overlaps with next tile's cp.async) ----
        #pragma unroll
        for (int m16 = 0; m16 < 2; m16++) {
            #pragma unroll
            for (int nt = 0; nt < 4; nt++) {
                #pragma unroll
                for (int e = 0; e < 4; e++) {
                    int rloc = m_warp * 32 + m16 * 16 + (lane >> 2) + ((e >> 1) << 3);
                    int c    = n_warp * 32 + nt * 8 + (lane & 3) * 2 + (e & 1);
                    int pp   = p0 + rloc;
                    int r0   = pp / 48;
                    int er   = bh * 48 + r0;
                    int ec   = bw * 48 + (pp - r0 * 48);
                    float v  = fmaxf(fmaf(d[m16][nt][e], ssc[c], sbi[c]), 0.f);
                    out[((size_t)(n * 64 + c) * HH + er) * WW + ec] = v;
                }
            }
        }
    }
}

// ---------------------------------------------------------------------------
extern "C" void kernel_launch(void* const* d_in, const int* in_sizes, int n_in,
                              void* d_out, int out_size) {
    const float* x      = (const float*)d_in[0];
    const float* conv_w = (const float*)d_in[1];
    const float* conv_b = (const float*)d_in[2];
    const float* gamma  = (const float*)d_in[3];
    const float* beta   = (const float*)d_in[4];
    const float* rmean  = (const float*)d_in[5];
    const float* rvar   = (const float*)d_in[6];
    const int*   abi    = (const int*)d_in[7];
    float* out = (float*)d_out;

    int nblk = in_sizes[7] / 3;   // 256

    cudaFuncSetAttribute(conv_kernel,
                         cudaFuncAttributeMaxDynamicSharedMemorySize, SMEM_TOTAL);

    prep_kernel<<<36, 1024>>>(conv_w, conv_b, gamma, beta, rmean, rvar);
    mask_kernel<<<1, 512>>>(abi, nblk);
    patch_kernel<<<dim3(50, nblk), 256>>>(x, abi);
    conv_kernel<<<512, 512, SMEM_TOTAL>>>(abi, out, nblk);
}